// round 7
// baseline (speedup 1.0000x reference)
#include <cuda_runtime.h>
#include <cstdint>
#include <cstddef>

#define BB 4
#define TT 2048
#define CC 1024
#define HH 16
#define HD 64
#define MROWS (BB*TT)          /* 8192 */
#define YN  (BB*TT*CC)         /* 8388608 */
#define KVN (BB*HH*TT*HD)      /* 8388608 */

// Scratch (allocation-free rule: __device__ globals)
__device__ float g_q[KVN];     // Q in [B,H,T,HD]
__device__ float g_att[YN];    // attention output in [B,T,C]

__device__ __forceinline__ float to_tf32(float x) {
    uint32_t u;
    asm("cvt.rna.tf32.f32 %0, %1;" : "=r"(u) : "f"(x));
    return __uint_as_float(u);
}

__device__ __forceinline__ void mma_tf32(
    float c[4], uint32_t a0, uint32_t a1, uint32_t a2, uint32_t a3,
    uint32_t b0, uint32_t b1)
{
    asm volatile(
        "mma.sync.aligned.m16n8k8.row.col.f32.tf32.tf32.f32 "
        "{%0,%1,%2,%3}, {%4,%5,%6,%7}, {%8,%9}, {%0,%1,%2,%3};\n"
        : "+f"(c[0]), "+f"(c[1]), "+f"(c[2]), "+f"(c[3])
        : "r"(a0), "r"(a1), "r"(a2), "r"(a3), "r"(b0), "r"(b1));
}

// ---------------------------------------------------------------------------
// TF32 tensor-core GEMM (unchanged, verified).
// ---------------------------------------------------------------------------
#define AST 36
#define BST 136
__global__ __launch_bounds__(256, 2) void gemm_tf32(
    const float* __restrict__ X, const float* __restrict__ W,
    const float* __restrict__ bias, float* __restrict__ out, int head_layout)
{
    __shared__ float As[128 * AST];
    __shared__ float Bs[32 * BST];

    const int tid  = threadIdx.x;
    const int bn   = blockIdx.x * 128, bm = blockIdx.y * 128;
    const int wid  = tid >> 5, lane = tid & 31;
    const int wm   = wid & 3,  wn   = wid >> 2;
    const int g    = lane >> 2, tg  = lane & 3;
    const int rb0  = wm * 32;
    const int cb0  = wn * 64;

    float acc[2][8][4];
    #pragma unroll
    for (int i = 0; i < 2; i++)
        #pragma unroll
        for (int j = 0; j < 8; j++)
            #pragma unroll
            for (int q = 0; q < 4; q++) acc[i][j][q] = 0.f;

    float4 pa[4], pb[4];
    #pragma unroll
    for (int i = 0; i < 4; i++) {
        int f = i * 256 + tid;
        int ra = f >> 3,  sa = f & 7;
        int rbr = f >> 5, sb = f & 31;
        pa[i] = *(const float4*)&X[(size_t)(bm + ra) * CC + sa * 4];
        pb[i] = *(const float4*)&W[(size_t)rbr * CC + bn + sb * 4];
    }

    for (int k0 = 0; k0 < CC; k0 += 32) {
        #pragma unroll
        for (int i = 0; i < 4; i++) {
            int f = i * 256 + tid;
            int ra = f >> 3, sa = f & 7;
            float* da = &As[ra * AST + sa * 4];
            da[0] = to_tf32(pa[i].x); da[1] = to_tf32(pa[i].y);
            da[2] = to_tf32(pa[i].z); da[3] = to_tf32(pa[i].w);
            int rbr = f >> 5, sb = f & 31;
            float* db = &Bs[rbr * BST + sb * 4];
            db[0] = to_tf32(pb[i].x); db[1] = to_tf32(pb[i].y);
            db[2] = to_tf32(pb[i].z); db[3] = to_tf32(pb[i].w);
        }
        __syncthreads();

        if (k0 + 32 < CC) {
            #pragma unroll
            for (int i = 0; i < 4; i++) {
                int f = i * 256 + tid;
                int ra = f >> 3,  sa = f & 7;
                int rbr = f >> 5, sb = f & 31;
                pa[i] = *(const float4*)&X[(size_t)(bm + ra) * CC + (k0 + 32) + sa * 4];
                pb[i] = *(const float4*)&W[(size_t)(k0 + 32 + rbr) * CC + bn + sb * 4];
            }
        }

        #pragma unroll
        for (int ks = 0; ks < 32; ks += 8) {
            uint32_t bf[8][2];
            #pragma unroll
            for (int j = 0; j < 8; j++) {
                int cb = cb0 + j * 8;
                bf[j][0] = __float_as_uint(Bs[(ks + tg)     * BST + cb + g]);
                bf[j][1] = __float_as_uint(Bs[(ks + tg + 4) * BST + cb + g]);
            }
            #pragma unroll
            for (int i = 0; i < 2; i++) {
                int rbm = rb0 + i * 16;
                uint32_t a0 = __float_as_uint(As[(rbm + g)     * AST + ks + tg]);
                uint32_t a1 = __float_as_uint(As[(rbm + g + 8) * AST + ks + tg]);
                uint32_t a2 = __float_as_uint(As[(rbm + g)     * AST + ks + tg + 4]);
                uint32_t a3 = __float_as_uint(As[(rbm + g + 8) * AST + ks + tg + 4]);
                #pragma unroll
                for (int j = 0; j < 8; j++)
                    mma_tf32(acc[i][j], a0, a1, a2, a3, bf[j][0], bf[j][1]);
            }
        }
        __syncthreads();
    }

    #pragma unroll
    for (int i = 0; i < 2; i++) {
        #pragma unroll
        for (int j = 0; j < 8; j++) {
            int n = bn + cb0 + j * 8 + tg * 2;
            float bs0 = bias[n], bs1 = bias[n + 1];
            #pragma unroll
            for (int half = 0; half < 2; half++) {
                int m = bm + rb0 + i * 16 + g + half * 8;
                float v0 = acc[i][j][half * 2 + 0] + bs0;
                float v1 = acc[i][j][half * 2 + 1] + bs1;
                if (head_layout) {
                    int b = m >> 11, t = m & 2047;
                    int h = n >> 6,  d = n & 63;
                    float* p = &out[((((size_t)b * HH + h) * TT + t) << 6) + d];
                    *(float2*)p = make_float2(v0, v1);
                } else {
                    *(float2*)&out[(size_t)m * CC + n] = make_float2(v0, v1);
                }
            }
        }
    }
}

// ---------------------------------------------------------------------------
// Tensor-core flash attention (causal, tf32 mma), software-pipelined.
// CTA: 128 q-rows x one (b,h). 8 warps, each owns m16 x n64 tiles.
// K/V for tile jt+1 are LDG-prefetched into registers while tile jt computes.
// ---------------------------------------------------------------------------
#define KST 72
#define VST 72
#define QST 68
__global__ __launch_bounds__(256) void attn_tc(
    const float* __restrict__ q, const float* __restrict__ kbase,
    const float* __restrict__ vbase, float* __restrict__ yout)
{
    __shared__ float sm[64 * KST + 64 * VST];   // 9216 floats = 36 KB
    float* Kts = sm;                 // [d][key], transposed K
    float* Vs  = sm + 64 * KST;      // [key][d]

    const int it  = blockIdx.x;      // q tile (128 rows)
    const int bh  = blockIdx.y;      // b*H + h
    const int tid = threadIdx.x;
    const int w   = tid >> 5, lane = tid & 31;
    const int g   = lane >> 2, tg = lane & 3;
    const int qbase = it * 128;
    const int w16   = w * 16;

    const float* Qg = q     + ((size_t)bh * TT + qbase) * HD;
    const float* Kg = kbase + (size_t)bh * TT * HD;
    const float* Vg = vbase + (size_t)bh * TT * HD;

    // Per-thread prefetch lane maps (fixed across tiles)
    int kkey[4], kch[4], vkey[4], vch[4];
    #pragma unroll
    for (int li = 0; li < 4; li++) {
        int i4 = li * 256 + tid;
        kkey[li] = i4 & 63; kch[li] = i4 >> 6;   // K: key-major
        vkey[li] = i4 >> 4; vch[li] = i4 & 15;   // V: chunk-major
    }

    // Issue tile-0 K/V loads immediately (overlap with Q staging)
    float4 pk[4], pv[4];
    #pragma unroll
    for (int li = 0; li < 4; li++) {
        pk[li] = *(const float4*)&Kg[(size_t)kkey[li] * HD + kch[li] * 4];
        pv[li] = *(const float4*)&Vg[(size_t)vkey[li] * HD + vch[li] * 4];
    }

    // --- Stage Q (x 1/8, tf32) into smem, build A-fragments in registers ---
    for (int i4 = tid; i4 < 2048; i4 += 256) {
        int r = i4 >> 4, c4 = (i4 & 15) * 4;
        float4 v = *(const float4*)&Qg[r * HD + c4];
        float* d = &sm[r * QST + c4];
        d[0] = to_tf32(0.125f * v.x); d[1] = to_tf32(0.125f * v.y);
        d[2] = to_tf32(0.125f * v.z); d[3] = to_tf32(0.125f * v.w);
    }
    __syncthreads();
    uint32_t qf[8][4];
    #pragma unroll
    for (int ks = 0; ks < 8; ks++) {
        qf[ks][0] = __float_as_uint(sm[(w16 + g)     * QST + ks * 8 + tg]);
        qf[ks][1] = __float_as_uint(sm[(w16 + g + 8) * QST + ks * 8 + tg]);
        qf[ks][2] = __float_as_uint(sm[(w16 + g)     * QST + ks * 8 + tg + 4]);
        qf[ks][3] = __float_as_uint(sm[(w16 + g + 8) * QST + ks * 8 + tg + 4]);
    }
    __syncthreads();   // Q staging done; Kts/Vs reuse the buffer

    float O[8][4];
    #pragma unroll
    for (int n8 = 0; n8 < 8; n8++)
        #pragma unroll
        for (int e = 0; e < 4; e++) O[n8][e] = 0.f;
    float mA = -1e30f, mB = -1e30f, lA = 0.f, lB = 0.f;

    const int diag_jt = 2 * it + (w >> 2);   // this warp's diagonal key tile
    const int ntiles  = 2 * it + 2;
    for (int jt = 0; jt < ntiles; jt++) {
        // Store prefetched tile into smem (tf32-converted)
        #pragma unroll
        for (int li = 0; li < 4; li++) {
            int key = kkey[li], ch = kch[li];
            Kts[(ch * 4 + 0) * KST + key] = to_tf32(pk[li].x);
            Kts[(ch * 4 + 1) * KST + key] = to_tf32(pk[li].y);
            Kts[(ch * 4 + 2) * KST + key] = to_tf32(pk[li].z);
            Kts[(ch * 4 + 3) * KST + key] = to_tf32(pk[li].w);
            *(float4*)&Vs[vkey[li] * VST + vch[li] * 4] =
                make_float4(to_tf32(pv[li].x), to_tf32(pv[li].y),
                            to_tf32(pv[li].z), to_tf32(pv[li].w));
        }
        __syncthreads();

        // Prefetch next tile while this one computes
        if (jt + 1 < ntiles) {
            const float* Kn = Kg + (size_t)(jt + 1) * 64 * HD;
            const float* Vn = Vg + (size_t)(jt + 1) * 64 * HD;
            #pragma unroll
            for (int li = 0; li < 4; li++) {
                pk[li] = *(const float4*)&Kn[(size_t)kkey[li] * HD + kch[li] * 4];
                pv[li] = *(const float4*)&Vn[(size_t)vkey[li] * HD + vch[li] * 4];
            }
        }

        // Tiles strictly after this warp's diagonal are fully masked: skip.
        if (jt <= diag_jt) {
            // ---- S = (Q/8) @ K^T  (scale pre-folded) ----
            float s[8][4];
            #pragma unroll
            for (int n8 = 0; n8 < 8; n8++)
                #pragma unroll
                for (int e = 0; e < 4; e++) s[n8][e] = 0.f;
            #pragma unroll
            for (int ks = 0; ks < 8; ks++) {
                #pragma unroll
                for (int n8 = 0; n8 < 8; n8++) {
                    uint32_t b0 = __float_as_uint(Kts[(ks * 8 + tg)     * KST + n8 * 8 + g]);
                    uint32_t b1 = __float_as_uint(Kts[(ks * 8 + tg + 4) * KST + n8 * 8 + g]);
                    mma_tf32(s[n8], qf[ks][0], qf[ks][1], qf[ks][2], qf[ks][3], b0, b1);
                }
            }

            // ---- causal mask on this warp's diagonal tile ----
            if (jt == diag_jt) {
                int r0 = (w & 3) * 16 + g, r1 = r0 + 8;  // rows rel. to key tile
                #pragma unroll
                for (int n8 = 0; n8 < 8; n8++) {
                    int k0 = n8 * 8 + 2 * tg, k1 = k0 + 1;
                    if (k0 > r0) s[n8][0] = -1e30f;
                    if (k1 > r0) s[n8][1] = -1e30f;
                    if (k0 > r1) s[n8][2] = -1e30f;
                    if (k1 > r1) s[n8][3] = -1e30f;
                }
            }

            // ---- online softmax (rows g and g+8; quad reduction) ----
            float tmA = -1e30f, tmB = -1e30f;
            #pragma unroll
            for (int n8 = 0; n8 < 8; n8++) {
                tmA = fmaxf(tmA, fmaxf(s[n8][0], s[n8][1]));
                tmB = fmaxf(tmB, fmaxf(s[n8][2], s[n8][3]));
            }
            tmA = fmaxf(tmA, __shfl_xor_sync(0xffffffffu, tmA, 1, 4));
            tmA = fmaxf(tmA, __shfl_xor_sync(0xffffffffu, tmA, 2, 4));
            tmB = fmaxf(tmB, __shfl_xor_sync(0xffffffffu, tmB, 1, 4));
            tmB = fmaxf(tmB, __shfl_xor_sync(0xffffffffu, tmB, 2, 4));
            float mnA = fmaxf(mA, tmA), mnB = fmaxf(mB, tmB);
            float cA = __expf(mA - mnA), cB = __expf(mB - mnB);
            mA = mnA; mB = mnB;
            float sA = 0.f, sB = 0.f;
            #pragma unroll
            for (int n8 = 0; n8 < 8; n8++) {
                s[n8][0] = __expf(s[n8][0] - mnA); sA += s[n8][0];
                s[n8][1] = __expf(s[n8][1] - mnA); sA += s[n8][1];
                s[n8][2] = __expf(s[n8][2] - mnB); sB += s[n8][2];
                s[n8][3] = __expf(s[n8][3] - mnB); sB += s[n8][3];
            }
            sA += __shfl_xor_sync(0xffffffffu, sA, 1, 4);
            sA += __shfl_xor_sync(0xffffffffu, sA, 2, 4);
            sB += __shfl_xor_sync(0xffffffffu, sB, 1, 4);
            sB += __shfl_xor_sync(0xffffffffu, sB, 2, 4);
            lA = lA * cA + sA;
            lB = lB * cB + sB;
            #pragma unroll
            for (int n8 = 0; n8 < 8; n8++) {
                O[n8][0] *= cA; O[n8][1] *= cA;
                O[n8][2] *= cB; O[n8][3] *= cB;
            }

            // ---- O += P @ V  (P C-frag -> A-frag via quad shuffles) ----
            const int base = lane & ~3;
            const int srcA = base | (tg >> 1);
            const int srcB = srcA + 2;
            const bool odd = (tg & 1);
            #pragma unroll
            for (int c = 0; c < 8; c++) {
                float v00 = __shfl_sync(0xffffffffu, s[c][0], srcA);
                float v01 = __shfl_sync(0xffffffffu, s[c][1], srcA);
                float v10 = __shfl_sync(0xffffffffu, s[c][0], srcB);
                float v11 = __shfl_sync(0xffffffffu, s[c][1], srcB);
                float w00 = __shfl_sync(0xffffffffu, s[c][2], srcA);
                float w01 = __shfl_sync(0xffffffffu, s[c][3], srcA);
                float w10 = __shfl_sync(0xffffffffu, s[c][2], srcB);
                float w11 = __shfl_sync(0xffffffffu, s[c][3], srcB);
                uint32_t a0 = __float_as_uint(to_tf32(odd ? v01 : v00)); // (g,   tg)
                uint32_t a1 = __float_as_uint(to_tf32(odd ? w01 : w00)); // (g+8, tg)
                uint32_t a2 = __float_as_uint(to_tf32(odd ? v11 : v10)); // (g,   tg+4)
                uint32_t a3 = __float_as_uint(to_tf32(odd ? w11 : w10)); // (g+8, tg+4)
                #pragma unroll
                for (int n8 = 0; n8 < 8; n8++) {
                    uint32_t b0 = __float_as_uint(Vs[(c * 8 + tg)     * VST + n8 * 8 + g]);
                    uint32_t b1 = __float_as_uint(Vs[(c * 8 + tg + 4) * VST + n8 * 8 + g]);
                    mma_tf32(O[n8], a0, a1, a2, a3, b0, b1);
                }
            }
        }
        __syncthreads();
    }

    // ---- epilogue: y[b, t, h*64 + d] = O / l ----
    float iA = 1.f / lA, iB = 1.f / lB;
    int b = bh >> 4, h = bh & 15;
    int row0 = qbase + w16 + g;
    #pragma unroll
    for (int n8 = 0; n8 < 8; n8++) {
        int col = h * 64 + n8 * 8 + 2 * tg;
        *(float2*)&yout[((size_t)b * TT + row0)     * CC + col] =
            make_float2(O[n8][0] * iA, O[n8][1] * iA);
        *(float2*)&yout[((size_t)b * TT + row0 + 8) * CC + col] =
            make_float2(O[n8][2] * iB, O[n8][3] * iB);
    }
}

// ---------------------------------------------------------------------------
extern "C" void kernel_launch(void* const* d_in, const int* in_sizes, int n_in,
                              void* d_out, int out_size)
{
    const float* x  = (const float*)d_in[0];
    const float* Wq = (const float*)d_in[2];
    const float* bq = (const float*)d_in[3];
    const float* Wk = (const float*)d_in[4];
    const float* bk = (const float*)d_in[5];
    const float* Wv = (const float*)d_in[6];
    const float* bv = (const float*)d_in[7];
    const float* Wp = (const float*)d_in[8];
    const float* bp = (const float*)d_in[9];

    float* out  = (float*)d_out;
    float* kout = out + YN;
    float* vout = out + YN + KVN;

    float *qbuf = nullptr, *abuf = nullptr;
    cudaGetSymbolAddress((void**)&qbuf, g_q);
    cudaGetSymbolAddress((void**)&abuf, g_att);

    dim3 gg(CC / 128, MROWS / 128);       // (8, 64)
    gemm_tf32<<<gg, 256>>>(x, Wq, bq, qbuf, 1);
    gemm_tf32<<<gg, 256>>>(x, Wk, bk, kout, 1);
    gemm_tf32<<<gg, 256>>>(x, Wv, bv, vout, 1);
    attn_tc<<<dim3(TT / 128, BB * HH), 256>>>(qbuf, kout, vout, abuf);
    gemm_tf32<<<gg, 256>>>(abuf, Wp, bp, out, 0);
}